// round 17
// baseline (speedup 1.0000x reference)
#include <cuda_runtime.h>
#include <cuda_fp16.h>
#include <cstdint>

// out[64,8192] = x[64,8192] @ blockdiag(blocks), 32 diagonal 256x256 blocks.
// Grid 128 = 32 blocks x 4 col-chunks of 64. Per CTA:
//   out[0:64, col0:col0+64] = x[0:64, k0:k0+256] @ B[k0:k0+256, col0:col0+64]
//
// Single-term fp16 HMMA (rel_err ~2.9e-4).
// R15: minimize L1 wavefronts. 16 warps = 2 K-halves x (4m x 2n) tiles of
// 16x32 (A x4 fragment reused across two B x4.trans -> 4 MMAs per kstep).
// LDSM wf/CTA: 3072 -> 1536. K-halves combined via 16KB smem reduce.

#define NROW 8192

#define OFF_AH  0          // 32KB: A fp16, 64 rows x 512B, swizzled
#define OFF_BH  32768      // 32KB: B fp16, 256 rows x 128B, swizzled
#define OFF_RED 65536      // 16KB: fp32 partials from K-half 1
#define SMEM_BYTES 81920

__device__ __forceinline__ uint32_t smem_u32(const void* p) {
    uint32_t a;
    asm("{ .reg .u64 t; cvta.to.shared.u64 t, %1; cvt.u32.u64 %0, t; }" : "=r"(a) : "l"(p));
    return a;
}
__device__ __forceinline__ void ldsm_x4(uint32_t* r, uint32_t addr) {
    asm volatile("ldmatrix.sync.aligned.m8n8.x4.shared.b16 {%0,%1,%2,%3}, [%4];"
                 : "=r"(r[0]), "=r"(r[1]), "=r"(r[2]), "=r"(r[3]) : "r"(addr));
}
__device__ __forceinline__ void ldsm_x4_t(uint32_t* r, uint32_t addr) {
    asm volatile("ldmatrix.sync.aligned.m8n8.x4.trans.shared.b16 {%0,%1,%2,%3}, [%4];"
                 : "=r"(r[0]), "=r"(r[1]), "=r"(r[2]), "=r"(r[3]) : "r"(addr));
}
__device__ __forceinline__ void mma_f16(float* d, const uint32_t* a, uint32_t b0, uint32_t b1) {
    asm volatile(
        "mma.sync.aligned.m16n8k16.row.col.f32.f16.f16.f32 "
        "{%0,%1,%2,%3}, {%4,%5,%6,%7}, {%8,%9}, {%0,%1,%2,%3};"
        : "+f"(d[0]), "+f"(d[1]), "+f"(d[2]), "+f"(d[3])
        : "r"(a[0]), "r"(a[1]), "r"(a[2]), "r"(a[3]), "r"(b0), "r"(b1));
}
__device__ __forceinline__ uint32_t h2u(__half2 h) { return *(uint32_t*)&h; }

__global__ void __launch_bounds__(512, 1)
block_diag_hmma(const float* __restrict__ x,
                const float* __restrict__ blocks,
                float* __restrict__ out) {
    extern __shared__ char smem[];
    const uint32_t sbase = smem_u32(smem);

    const int tid   = threadIdx.x;
    const int wid   = tid >> 5;
    const int lid   = tid & 31;
    const int bx    = blockIdx.x;
    const int dblk  = bx >> 2;
    const int chunk = bx & 3;
    const int k0    = dblk * 256;
    const int col0  = k0 + chunk * 64;

    // ================= stage phase =================
    // B first (unique bytes), then A; 8 f4 each per thread, cvt+STS inline.
    {
        char* Bh = smem + OFF_BH;
        #pragma unroll
        for (int p = 0; p < 8; ++p) {
            int idx = p * 512 + tid;
            int k  = idx >> 4;            // 0..255
            int n4 = idx & 15;            // f4 along 64 cols
            float4 v = *(const float4*)(blocks + (size_t)(k0 + k) * NROW + col0 + n4 * 4);
            int g = n4 >> 1;
            uint32_t off = (uint32_t)(k * 128 + ((g ^ (k & 7)) * 16) + (n4 & 1) * 8);
            __half2 b01 = __floats2half2_rn(v.x, v.y);
            __half2 b23 = __floats2half2_rn(v.z, v.w);
            *(uint32_t*)(Bh + off)     = h2u(b01);
            *(uint32_t*)(Bh + off + 4) = h2u(b23);
        }
        char* Ah = smem + OFF_AH;
        #pragma unroll
        for (int p = 0; p < 8; ++p) {
            int idx = p * 512 + tid;
            int m = idx >> 6;             // 0..63
            int q = idx & 63;             // f4 along K
            float4 v = *(const float4*)(x + (size_t)m * NROW + k0 + q * 4);
            int g = q >> 1;
            uint32_t off = (uint32_t)(m * 512 + ((g ^ (m & 7)) * 16) + (q & 1) * 8);
            __half2 a01 = __floats2half2_rn(v.x, v.y);
            __half2 a23 = __floats2half2_rn(v.z, v.w);
            *(uint32_t*)(Ah + off)     = h2u(a01);
            *(uint32_t*)(Ah + off + 4) = h2u(a23);
        }
    }

    __syncthreads();

    // ================= compute phase =================
    // 16 warps = 2 K-halves (h) x 4m x 2n; warp tile 16x32; 8 ksteps per half.
    const int h   = wid >> 3;             // K-half
    const int wl  = wid & 7;
    const int wm  = wl & 3;
    const int wn2 = wl >> 2;              // 0/1 -> n_base 0/32
    const int m_base = wm * 16;
    const int n_base = wn2 * 32;

    const int a_row = m_base + (lid & 15);
    const int a_ch  = lid >> 4;
    const int a_rx  = a_row & 7;
    const uint32_t a_rowbase = sbase + OFF_AH + (uint32_t)(a_row * 512);

    const int l15 = lid & 15;
    const int l7  = lid & 7;
    // two B n-tiles: t0 = wn2*2, t1 = wn2*2+1
    const uint32_t b_lane0 = sbase + OFF_BH
        + (uint32_t)(l15 * 128 + (((wn2 * 4 + 0 + (lid >> 4)) ^ l7) * 16));
    const uint32_t b_lane1 = sbase + OFF_BH
        + (uint32_t)(l15 * 128 + (((wn2 * 4 + 2 + (lid >> 4)) ^ l7) * 16));

    float acc[4][4] = {};                  // 4 n-subtiles of 8 cols
    uint32_t a[4], b0[4], b1[4];

    #pragma unroll
    for (int ks = 0; ks < 8; ++ks) {
        int G = (h * 8 + ks) * 2 + a_ch;   // global 16B granule along K
        uint32_t a_off = a_rowbase + (uint32_t)((G ^ a_rx) * 16);
        uint32_t brow  = (uint32_t)((h * 8 + ks) * 2048);   // 16 k-rows x 128B
        ldsm_x4(a, a_off);
        ldsm_x4_t(b0, b_lane0 + brow);
        ldsm_x4_t(b1, b_lane1 + brow);
        mma_f16(acc[0], a, b0[0], b0[1]);
        mma_f16(acc[1], a, b0[2], b0[3]);
        mma_f16(acc[2], a, b1[0], b1[1]);
        mma_f16(acc[3], a, b1[2], b1[3]);
    }

    // ================= K-reduce + store =================
    // half 1 -> smem partials; half 0 adds and stores.
    float* red = (float*)(smem + OFF_RED);   // [8 warps][32 lanes][16 floats]
    if (h == 1) {
        float4* dst = (float4*)(red + (wl * 32 + lid) * 16);
        #pragma unroll
        for (int s = 0; s < 4; ++s)
            dst[s] = make_float4(acc[s][0], acc[s][1], acc[s][2], acc[s][3]);
    }
    __syncthreads();
    if (h == 0) {
        const float4* src = (const float4*)(red + (wl * 32 + lid) * 16);
        const int grp = lid >> 2;
        const int tc  = lid & 3;
        const int row0 = m_base + grp;
        const int row1 = row0 + 8;
        #pragma unroll
        for (int s = 0; s < 4; ++s) {
            float4 p = src[s];
            int col = col0 + n_base + s * 8 + tc * 2;
            *(float2*)(out + (size_t)row0 * NROW + col)
                = make_float2(acc[s][0] + p.x, acc[s][1] + p.y);
            *(float2*)(out + (size_t)row1 * NROW + col)
                = make_float2(acc[s][2] + p.z, acc[s][3] + p.w);
        }
    }
}

extern "C" void kernel_launch(void* const* d_in, const int* in_sizes, int n_in,
                              void* d_out, int out_size) {
    const float* x      = (const float*)d_in[0];
    const float* blocks = (const float*)d_in[1];
    float* out = (float*)d_out;

    cudaFuncSetAttribute(block_diag_hmma,
                         cudaFuncAttributeMaxDynamicSharedMemorySize, SMEM_BYTES);
    block_diag_hmma<<<128, 512, SMEM_BYTES>>>(x, blocks, out);
}